// round 9
// baseline (speedup 1.0000x reference)
#include <cuda_runtime.h>
#include <cuda_fp16.h>

#define B    4
#define LQ   512
#define LK   512
#define E    128
#define D    256
#define TL   8            // l-rows per score/context CTA
#define QT   32           // qq per stage tile
#define QBLK 128          // qq per score-CTA
#define NTA  (QBLK / QT)  // 4 tiles per score-CTA
#define NTHR 256

// Scratch (allocation-free rule: __device__ globals)
__device__ float g_qproj[B * LQ * E];
__device__ float g_kproj[B * LK * E];
__device__ float g_scores[B * LK * LQ];   // raw scores (pre-softmax)

__device__ __forceinline__ __half2 tanh_h2(__half2 x) {
    unsigned xu = *reinterpret_cast<unsigned*>(&x);
    unsigned r;
    asm("tanh.approx.f16x2 %0, %1;" : "=r"(r) : "r"(xu));
    return *reinterpret_cast<__half2*>(&r);
}
__device__ __forceinline__ void cpasync16(void* smem_dst, const void* gsrc) {
    unsigned s = (unsigned)__cvta_generic_to_shared(smem_dst);
    asm volatile("cp.async.cg.shared.global [%0], [%1], 16;" :: "r"(s), "l"(gsrc));
}

// ---------------------------------------------------------------------------
// Projection: out[r][e] = sum_d X[r][d] * W[d][e].
// 8 rows/CTA -> 512 CTAs (W L2 traffic 67MB, occ ~3.5 CTA/SM) with explicit
// software pipelining: register double-buffer w/wn so chunk d0's FFMAs overlap
// chunk d0+8's 8 independent LDG.64 (one full chunk of latency tolerance).
// 256 thr: thread = (ep = e-pair 0..63, rg = 0..3 -> rows 2rg, 2rg+1).
// ---------------------------------------------------------------------------
__global__ __launch_bounds__(NTHR) void proj_kernel(
    const float* __restrict__ query, const float* __restrict__ key,
    const float* __restrict__ Wc1,   const float* __restrict__ Wc2)
{
    const float* X; const float* W; float* O;
    if (blockIdx.y == 0) { X = query; W = Wc1; O = g_qproj; }
    else                 { X = key;   W = Wc2; O = g_kproj; }

    const int row0 = blockIdx.x * 8;
    const int tid  = threadIdx.x;
    const int ep   = tid & 63;           // e-pair 0..63 (E/2)
    const int rg   = tid >> 6;           // 0..3 -> rows 2rg, 2rg+1

    __shared__ float xs[8 * D];          // 8 KB
    const float4* xv = (const float4*)(X + (size_t)row0 * D);
    #pragma unroll
    for (int i = tid; i < 8 * D / 4; i += NTHR)
        ((float4*)xs)[i] = xv[i];
    __syncthreads();

    const float2* Wp  = (const float2*)W;          // [D][E/2]
    const float*  x0s = xs + (2 * rg + 0) * D;
    const float*  x1s = xs + (2 * rg + 1) * D;

    float2 w[8], wn[8];
    #pragma unroll
    for (int j = 0; j < 8; j++)                    // prologue: chunk 0
        w[j] = Wp[j * (E / 2) + ep];

    float2 a0 = make_float2(0.f, 0.f), a1 = a0;
    #pragma unroll 2
    for (int d0 = 0; d0 < D; d0 += 8) {
        if (d0 + 8 < D) {
            #pragma unroll
            for (int j = 0; j < 8; j++)            // prefetch chunk d0+8 (MLP 8)
                wn[j] = Wp[(d0 + 8 + j) * (E / 2) + ep];
        }
        #pragma unroll
        for (int j = 0; j < 8; j++) {              // compute chunk d0
            float x0 = x0s[d0 + j];                // warp-uniform LDS broadcast
            float x1 = x1s[d0 + j];
            a0.x += x0 * w[j].x; a0.y += x0 * w[j].y;
            a1.x += x1 * w[j].x; a1.y += x1 * w[j].y;
        }
        #pragma unroll
        for (int j = 0; j < 8; j++) w[j] = wn[j];  // rotate (reg-renamed by unroll 2)
    }
    float2* Op = (float2*)O;
    Op[(size_t)(row0 + 2 * rg + 0) * (E / 2) + ep] = a0;
    Op[(size_t)(row0 + 2 * rg + 1) * (E / 2) + ep] = a1;
}

// ---------------------------------------------------------------------------
// Score kernel: raw scores -> g_scores.
// Grid (LQ/QBLK=4, LK/TL=64, B=4) = 1024 CTAs, 256 thr, occ target 7.
// (unchanged — measured part of the win)
// ---------------------------------------------------------------------------
__global__ __launch_bounds__(NTHR, 7) void score_kernel(
    const float* __restrict__ vc, float* __restrict__ sc_out)
{
    const int qblk = blockIdx.x;
    const int l0   = blockIdx.y * TL;
    const int b    = blockIdx.z;
    const int tid  = threadIdx.x;
    const int w    = tid >> 5;
    const int lane = tid & 31;

    __shared__ float   ks[TL][132];      // 4.2 KB padded
    __shared__ __half2 vcs[E / 2];       // 256 B
    __shared__ float   qs[QT][132];      // 16.9 KB single buffer, padded

    for (int i = tid; i < TL * E; i += NTHR)
        ks[i >> 7][i & 127] = g_kproj[(size_t)(b * LK + l0 + (i >> 7)) * E + (i & 127)];
    if (tid < E / 2)
        vcs[tid] = __floats2half2_rn(vc[2 * tid], vc[2 * tid + 1]);

    const float4* qbase = (const float4*)(g_qproj + ((size_t)b * LQ + qblk * QBLK) * E);

    const int lrow = lane >> 2;              // 0..7
    const int qrow = w * 4 + (lane & 3);     // 0..31 within tile
    float* orow = sc_out + (size_t)(b * LK + l0 + lrow) * LQ + qblk * QBLK + qrow;

    #pragma unroll 1
    for (int t = 0; t < NTA; t++) {
        __syncthreads();                     // qs free (covers ks/vcs at t=0)
        const float4* src = qbase + t * (QT * E / 4);
        #pragma unroll
        for (int j = 0; j < 4; j++) {
            int i = tid + j * NTHR;          // 0..1023 float4s
            cpasync16(&qs[i >> 5][(i & 31) * 4], src + i);
        }
        asm volatile("cp.async.commit_group;");
        asm volatile("cp.async.wait_group 0;");
        __syncthreads();                     // qs visible

        const float4* qp = (const float4*)qs[qrow];
        const float4* kp = (const float4*)ks[lrow];
        const uint2*  vp = (const uint2*)vcs;

        float facc = 0.f;
        #pragma unroll 4
        for (int c = 0; c < E / 16; c++) {               // 8 chunks of 16 e
            __half2 acc01 = __float2half2_rn(0.f);
            __half2 acc23 = __float2half2_rn(0.f);
            #pragma unroll
            for (int u = 0; u < 4; u++) {
                const int e4 = c * 4 + u;
                float4 q = qp[e4];                       // 1 phase (8-way dup)
                float4 k = kp[e4];                       // 1 phase (4-way dup)
                uint2  v = vp[e4];                       // broadcast
                __half2 h01 = __floats2half2_rn(q.x + k.x, q.y + k.y);
                __half2 h23 = __floats2half2_rn(q.z + k.z, q.w + k.w);
                __half2 t01 = tanh_h2(h01);
                __half2 t23 = tanh_h2(h23);
                __half2 v01 = *reinterpret_cast<__half2*>(&v.x);
                __half2 v23 = *reinterpret_cast<__half2*>(&v.y);
                acc01 = __hfma2(v01, t01, acc01);
                acc23 = __hfma2(v23, t23, acc23);
            }
            float2 f01 = __half22float2(acc01);
            float2 f23 = __half22float2(acc23);
            facc += (f01.x + f01.y) + (f23.x + f23.y);
        }
        orow[t * QT] = facc;                              // raw score
    }
}

// ---------------------------------------------------------------------------
// Fused softmax + context. Grid (2 D-halves, LK/TL=64, B) = 512 CTAs, 256 thr.
// (unchanged — measured part of the win)
// ---------------------------------------------------------------------------
__global__ __launch_bounds__(NTHR, 4) void context_kernel(
    const float* __restrict__ value, const float* __restrict__ scores,
    float* __restrict__ att_out, float* __restrict__ ctx_out)
{
    const int dsl = blockIdx.x;              // 0..1 : D-half
    const int l0  = blockIdx.y * TL;
    const int b   = blockIdx.z;
    const int tid = threadIdx.x;
    const int w   = tid >> 5;                // warp = l-row (softmax) = qq block (gemm)
    const int lane = tid & 31;

    __shared__ float  ps[TL][LQ];            // 16 KB probabilities
    __shared__ float4 red[TL][TL][32];       // 32 KB partials [qg][l][d4g]

    // ---- softmax (warp w owns row l0 + w) ----
    {
        const float4* srow = (const float4*)(scores + (size_t)(b * LK + l0 + w) * LQ);
        float4 v[4];
        float m = -1e30f;
        #pragma unroll
        for (int k = 0; k < 4; k++) {
            v[k] = srow[lane + 32 * k];
            m = fmaxf(m, fmaxf(fmaxf(v[k].x, v[k].y), fmaxf(v[k].z, v[k].w)));
        }
        #pragma unroll
        for (int o = 16; o; o >>= 1) m = fmaxf(m, __shfl_xor_sync(0xffffffffu, m, o));
        float s = 0.f;
        #pragma unroll
        for (int k = 0; k < 4; k++) {
            v[k].x = __expf(v[k].x - m); v[k].y = __expf(v[k].y - m);
            v[k].z = __expf(v[k].z - m); v[k].w = __expf(v[k].w - m);
            s += (v[k].x + v[k].y) + (v[k].z + v[k].w);
        }
        #pragma unroll
        for (int o = 16; o; o >>= 1) s += __shfl_xor_sync(0xffffffffu, s, o);
        const float inv = __fdividef(1.f, s);

        float4* prow = (float4*)ps[w];
        float4* arow = (float4*)(att_out + (size_t)(b * LK + l0 + w) * LQ);
        #pragma unroll
        for (int k = 0; k < 4; k++) {
            v[k].x *= inv; v[k].y *= inv; v[k].z *= inv; v[k].w *= inv;
            prow[lane + 32 * k] = v[k];          // conflict-free STS.128
            if (dsl == 0) arow[lane + 32 * k] = v[k];
        }
    }
    __syncthreads();

    // ---- context GEMM: D-half dsl, qq block w ----
    const float4* vbase = (const float4*)(value + (size_t)b * LQ * D) + dsl * 32 + lane;

    float4 acc[TL];
    #pragma unroll
    for (int l = 0; l < TL; l++) acc[l] = make_float4(0.f, 0.f, 0.f, 0.f);

    const int q0 = w * 64;
    #pragma unroll 2
    for (int qc = 0; qc < 64; qc += 4) {
        const int qq = q0 + qc;
        float4 v0 = vbase[(qq + 0) * (D / 4)];
        float4 v1 = vbase[(qq + 1) * (D / 4)];
        float4 v2 = vbase[(qq + 2) * (D / 4)];
        float4 v3 = vbase[(qq + 3) * (D / 4)];
        #pragma unroll
        for (int l = 0; l < TL; l++) {
            float4 p = *(const float4*)&ps[l][qq];   // broadcast LDS.128
            acc[l].x += p.x * v0.x; acc[l].y += p.x * v0.y;
            acc[l].z += p.x * v0.z; acc[l].w += p.x * v0.w;
            acc[l].x += p.y * v1.x; acc[l].y += p.y * v1.y;
            acc[l].z += p.y * v1.z; acc[l].w += p.y * v1.w;
            acc[l].x += p.z * v2.x; acc[l].y += p.z * v2.y;
            acc[l].z += p.z * v2.z; acc[l].w += p.z * v2.w;
            acc[l].x += p.w * v3.x; acc[l].y += p.w * v3.y;
            acc[l].z += p.w * v3.z; acc[l].w += p.w * v3.w;
        }
    }

    #pragma unroll
    for (int l = 0; l < TL; l++)
        red[w][l][lane] = acc[l];
    __syncthreads();

    // thread (lane, w) reduces 8 partials for l-row w, its d4 column
    float4 c = make_float4(0.f, 0.f, 0.f, 0.f);
    #pragma unroll
    for (int g = 0; g < TL; g++) {
        float4 r = red[g][w][lane];
        c.x += r.x; c.y += r.y; c.z += r.z; c.w += r.w;
    }
    ((float4*)ctx_out)[(size_t)(b * LK + l0 + w) * (D / 4) + dsl * 32 + lane] = c;
}

// ---------------------------------------------------------------------------
extern "C" void kernel_launch(void* const* d_in, const int* in_sizes, int n_in,
                              void* d_out, int out_size)
{
    const float* query = (const float*)d_in[0];
    const float* key   = (const float*)d_in[1];
    const float* value = (const float*)d_in[2];
    const float* Wc1   = (const float*)d_in[3];
    const float* Wc2   = (const float*)d_in[4];
    const float* vc    = (const float*)d_in[5];

    float* ctx = (float*)d_out;                 // [B, LK, D]
    float* att = ctx + (size_t)B * LK * D;      // [B, LK, LQ]

    float* sc;
    cudaGetSymbolAddress((void**)&sc, g_scores);

    proj_kernel<<<dim3(B * LQ / 8, 2), NTHR>>>(query, key, Wc1, Wc2);
    score_kernel<<<dim3(LQ / QBLK, LK / TL, B), NTHR>>>(vc, sc);
    context_kernel<<<dim3(2, LK / TL, B), NTHR>>>(value, sc, att, ctx);
}

// round 11
// speedup vs baseline: 1.0584x; 1.0584x over previous
#include <cuda_runtime.h>
#include <cuda_fp16.h>

#define B    4
#define LQ   512
#define LK   512
#define E    128
#define D    256
#define TL   8            // l-rows per score/context CTA
#define QT   32           // qq per stage tile
#define QBLK 128          // qq per score-CTA
#define NTA  (QBLK / QT)  // 4 tiles per score-CTA
#define NTHR 256
#define QPAD 68           // half2 row stride (272B): rows bank-shifted by 4
#define TILE_F4 (QT * (E / 2) / 4)   // float4 per q tile = 512

// Scratch (allocation-free rule: __device__ globals). Projections in half2.
__device__ __half2 g_qproj[B * LQ * (E / 2)];
__device__ __half2 g_kproj[B * LK * (E / 2)];
__device__ float   g_scores[B * LK * LQ];   // raw scores (pre-softmax)

__device__ __forceinline__ __half2 tanh_h2(__half2 x) {
    unsigned xu = *reinterpret_cast<unsigned*>(&x);
    unsigned r;
    asm("tanh.approx.f16x2 %0, %1;" : "=r"(r) : "r"(xu));
    return *reinterpret_cast<__half2*>(&r);
}
__device__ __forceinline__ __half2 u2h(unsigned x) {
    __half2 h; *reinterpret_cast<unsigned*>(&h) = x; return h;
}
__device__ __forceinline__ void cpasync16(void* smem_dst, const void* gsrc) {
    unsigned s = (unsigned)__cvta_generic_to_shared(smem_dst);
    asm volatile("cp.async.cg.shared.global [%0], [%1], 16;" :: "r"(s), "l"(gsrc));
}

// ---------------------------------------------------------------------------
// Projection: out[r][e] = sum_d X[r][d] * W[d][e]; f32 accumulate, half2 store.
// 8 rows/CTA -> 512 CTAs, register double-buffered W prefetch (MLP 8).
// ---------------------------------------------------------------------------
__global__ __launch_bounds__(NTHR) void proj_kernel(
    const float* __restrict__ query, const float* __restrict__ key,
    const float* __restrict__ Wc1,   const float* __restrict__ Wc2)
{
    const float* X; const float* W; __half2* O;
    if (blockIdx.y == 0) { X = query; W = Wc1; O = g_qproj; }
    else                 { X = key;   W = Wc2; O = g_kproj; }

    const int row0 = blockIdx.x * 8;
    const int tid  = threadIdx.x;
    const int ep   = tid & 63;           // e-pair 0..63 (E/2)
    const int rg   = tid >> 6;           // 0..3 -> rows 2rg, 2rg+1

    __shared__ float xs[8 * D];          // 8 KB
    const float4* xv = (const float4*)(X + (size_t)row0 * D);
    #pragma unroll
    for (int i = tid; i < 8 * D / 4; i += NTHR)
        ((float4*)xs)[i] = xv[i];
    __syncthreads();

    const float2* Wp  = (const float2*)W;          // [D][E/2]
    const float*  x0s = xs + (2 * rg + 0) * D;
    const float*  x1s = xs + (2 * rg + 1) * D;

    float2 w[8], wn[8];
    #pragma unroll
    for (int j = 0; j < 8; j++)                    // prologue: chunk 0
        w[j] = Wp[j * (E / 2) + ep];

    float2 a0 = make_float2(0.f, 0.f), a1 = a0;
    #pragma unroll 2
    for (int d0 = 0; d0 < D; d0 += 8) {
        if (d0 + 8 < D) {
            #pragma unroll
            for (int j = 0; j < 8; j++)            // prefetch chunk d0+8 (MLP 8)
                wn[j] = Wp[(d0 + 8 + j) * (E / 2) + ep];
        }
        #pragma unroll
        for (int j = 0; j < 8; j++) {              // compute chunk d0
            float x0 = x0s[d0 + j];                // warp-uniform LDS broadcast
            float x1 = x1s[d0 + j];
            a0.x += x0 * w[j].x; a0.y += x0 * w[j].y;
            a1.x += x1 * w[j].x; a1.y += x1 * w[j].y;
        }
        #pragma unroll
        for (int j = 0; j < 8; j++) w[j] = wn[j];
    }
    O[(size_t)(row0 + 2 * rg + 0) * (E / 2) + ep] = __floats2half2_rn(a0.x, a0.y);
    O[(size_t)(row0 + 2 * rg + 1) * (E / 2) + ep] = __floats2half2_rn(a1.x, a1.y);
}

// ---------------------------------------------------------------------------
// Score kernel: raw scores -> g_scores, pure-half2 inner loop.
// Grid (LQ/QBLK=4, LK/TL=64, B=4) = 1024 CTAs, 256 thr, occ 7.
// Per 4 e: 3 LDS.64 + 2 HADD2 + 2 MUFU(tanh.f16x2) + 2 HFMA2 = 9 instrs.
// FIX vs R10: tile advance = TILE_F4 (512 float4/tile), was wrongly 256.
// ---------------------------------------------------------------------------
__global__ __launch_bounds__(NTHR, 7) void score_kernel(
    const float* __restrict__ vc, float* __restrict__ sc_out)
{
    const int qblk = blockIdx.x;
    const int l0   = blockIdx.y * TL;
    const int b    = blockIdx.z;
    const int tid  = threadIdx.x;
    const int w    = tid >> 5;
    const int lane = tid & 31;

    __shared__ __align__(16) __half2 ks[TL][QPAD];       // 2.2 KB
    __shared__ __align__(16) __half2 vcs[E / 2];         // 256 B
    __shared__ __align__(16) __half2 qs[2][QT][QPAD];    // 17.4 KB double buffer

    for (int i = tid; i < TL * (E / 2); i += NTHR)
        ks[i >> 6][i & 63] = g_kproj[(size_t)(b * LK + l0 + (i >> 6)) * (E / 2) + (i & 63)];
    if (tid < E / 2)
        vcs[tid] = __floats2half2_rn(vc[2 * tid], vc[2 * tid + 1]);

    // q tile source: rows of 64 half2 = 256B = 16 float4 each
    const float4* qbase = (const float4*)(g_qproj + ((size_t)b * LQ + qblk * QBLK) * (E / 2));

    // stage tile 0 into buffer 0 (TILE_F4 = 512 float4 per tile, 2 per thread)
    #pragma unroll
    for (int j = 0; j < 2; j++) {
        int i = tid + j * NTHR;                  // 0..511
        cpasync16(&qs[0][i >> 4][(i & 15) * 4], qbase + i);
    }
    asm volatile("cp.async.commit_group;");

    const int lrow = lane >> 2;              // 0..7
    const int qrow = w * 4 + (lane & 3);     // 0..31 within tile
    float* orow = sc_out + (size_t)(b * LK + l0 + lrow) * LQ + qblk * QBLK + qrow;

    #pragma unroll 1
    for (int t = 0; t < NTA; t++) {
        __syncthreads();                     // prev reads of buf[(t+1)&1] done
        if (t + 1 < NTA) {
            const float4* src = qbase + (size_t)(t + 1) * TILE_F4;   // FIXED
            #pragma unroll
            for (int j = 0; j < 2; j++) {
                int i = tid + j * NTHR;
                cpasync16(&qs[(t + 1) & 1][i >> 4][(i & 15) * 4], src + i);
            }
            asm volatile("cp.async.commit_group;");
            asm volatile("cp.async.wait_group 1;");   // tile t landed
        } else {
            asm volatile("cp.async.wait_group 0;");
        }
        __syncthreads();                     // tile t visible

        const uint2* qp = (const uint2*)qs[t & 1][qrow];
        const uint2* kp = (const uint2*)ks[lrow];
        const uint2* vp = (const uint2*)vcs;

        float facc = 0.f;
        #pragma unroll 4
        for (int c = 0; c < E / 16; c++) {               // 8 chunks of 16 e
            __half2 acc01 = __float2half2_rn(0.f);
            __half2 acc23 = __float2half2_rn(0.f);
            #pragma unroll
            for (int u = 0; u < 4; u++) {
                const int e4 = c * 4 + u;
                uint2 q = qp[e4];                        // 1 phase (8-way dup)
                uint2 k = kp[e4];                        // 1 phase (4-way dup)
                uint2 v = vp[e4];                        // broadcast
                __half2 t01 = tanh_h2(__hadd2(u2h(q.x), u2h(k.x)));
                __half2 t23 = tanh_h2(__hadd2(u2h(q.y), u2h(k.y)));
                acc01 = __hfma2(u2h(v.x), t01, acc01);
                acc23 = __hfma2(u2h(v.y), t23, acc23);
            }
            float2 f01 = __half22float2(acc01);
            float2 f23 = __half22float2(acc23);
            facc += (f01.x + f01.y) + (f23.x + f23.y);
        }
        orow[t * QT] = facc;                              // raw score (f32)
    }
}

// ---------------------------------------------------------------------------
// Fused softmax + context. Grid (2 D-halves, LK/TL=64, B) = 512 CTAs, 256 thr.
// (unchanged — measured good)
// ---------------------------------------------------------------------------
__global__ __launch_bounds__(NTHR, 4) void context_kernel(
    const float* __restrict__ value, const float* __restrict__ scores,
    float* __restrict__ att_out, float* __restrict__ ctx_out)
{
    const int dsl = blockIdx.x;              // 0..1 : D-half
    const int l0  = blockIdx.y * TL;
    const int b   = blockIdx.z;
    const int tid = threadIdx.x;
    const int w   = tid >> 5;                // warp = l-row (softmax) = qq block (gemm)
    const int lane = tid & 31;

    __shared__ float  ps[TL][LQ];            // 16 KB probabilities
    __shared__ float4 red[TL][TL][32];       // 32 KB partials [qg][l][d4g]

    // ---- softmax (warp w owns row l0 + w) ----
    {
        const float4* srow = (const float4*)(scores + (size_t)(b * LK + l0 + w) * LQ);
        float4 v[4];
        float m = -1e30f;
        #pragma unroll
        for (int k = 0; k < 4; k++) {
            v[k] = srow[lane + 32 * k];
            m = fmaxf(m, fmaxf(fmaxf(v[k].x, v[k].y), fmaxf(v[k].z, v[k].w)));
        }
        #pragma unroll
        for (int o = 16; o; o >>= 1) m = fmaxf(m, __shfl_xor_sync(0xffffffffu, m, o));
        float s = 0.f;
        #pragma unroll
        for (int k = 0; k < 4; k++) {
            v[k].x = __expf(v[k].x - m); v[k].y = __expf(v[k].y - m);
            v[k].z = __expf(v[k].z - m); v[k].w = __expf(v[k].w - m);
            s += (v[k].x + v[k].y) + (v[k].z + v[k].w);
        }
        #pragma unroll
        for (int o = 16; o; o >>= 1) s += __shfl_xor_sync(0xffffffffu, s, o);
        const float inv = __fdividef(1.f, s);

        float4* prow = (float4*)ps[w];
        float4* arow = (float4*)(att_out + (size_t)(b * LK + l0 + w) * LQ);
        #pragma unroll
        for (int k = 0; k < 4; k++) {
            v[k].x *= inv; v[k].y *= inv; v[k].z *= inv; v[k].w *= inv;
            prow[lane + 32 * k] = v[k];          // conflict-free STS.128
            if (dsl == 0) arow[lane + 32 * k] = v[k];
        }
    }
    __syncthreads();

    // ---- context GEMM: D-half dsl, qq block w ----
    const float4* vbase = (const float4*)(value + (size_t)b * LQ * D) + dsl * 32 + lane;

    float4 acc[TL];
    #pragma unroll
    for (int l = 0; l < TL; l++) acc[l] = make_float4(0.f, 0.f, 0.f, 0.f);

    const int q0 = w * 64;
    #pragma unroll 2
    for (int qc = 0; qc < 64; qc += 4) {
        const int qq = q0 + qc;
        float4 v0 = vbase[(qq + 0) * (D / 4)];
        float4 v1 = vbase[(qq + 1) * (D / 4)];
        float4 v2 = vbase[(qq + 2) * (D / 4)];
        float4 v3 = vbase[(qq + 3) * (D / 4)];
        #pragma unroll
        for (int l = 0; l < TL; l++) {
            float4 p = *(const float4*)&ps[l][qq];   // broadcast LDS.128
            acc[l].x += p.x * v0.x; acc[l].y += p.x * v0.y;
            acc[l].z += p.x * v0.z; acc[l].w += p.x * v0.w;
            acc[l].x += p.y * v1.x; acc[l].y += p.y * v1.y;
            acc[l].z += p.y * v1.z; acc[l].w += p.y * v1.w;
            acc[l].x += p.z * v2.x; acc[l].y += p.z * v2.y;
            acc[l].z += p.z * v2.z; acc[l].w += p.z * v2.w;
            acc[l].x += p.w * v3.x; acc[l].y += p.w * v3.y;
            acc[l].z += p.w * v3.z; acc[l].w += p.w * v3.w;
        }
    }

    #pragma unroll
    for (int l = 0; l < TL; l++)
        red[w][l][lane] = acc[l];
    __syncthreads();

    float4 c = make_float4(0.f, 0.f, 0.f, 0.f);
    #pragma unroll
    for (int g = 0; g < TL; g++) {
        float4 r = red[g][w][lane];
        c.x += r.x; c.y += r.y; c.z += r.z; c.w += r.w;
    }
    ((float4*)ctx_out)[(size_t)(b * LK + l0 + w) * (D / 4) + dsl * 32 + lane] = c;
}

// ---------------------------------------------------------------------------
extern "C" void kernel_launch(void* const* d_in, const int* in_sizes, int n_in,
                              void* d_out, int out_size)
{
    const float* query = (const float*)d_in[0];
    const float* key   = (const float*)d_in[1];
    const float* value = (const float*)d_in[2];
    const float* Wc1   = (const float*)d_in[3];
    const float* Wc2   = (const float*)d_in[4];
    const float* vc    = (const float*)d_in[5];

    float* ctx = (float*)d_out;                 // [B, LK, D]
    float* att = ctx + (size_t)B * LK * D;      // [B, LK, LQ]

    float* sc;
    cudaGetSymbolAddress((void**)&sc, g_scores);

    proj_kernel<<<dim3(B * LQ / 8, 2), NTHR>>>(query, key, Wc1, Wc2);
    score_kernel<<<dim3(LQ / QBLK, LK / TL, B), NTHR>>>(vc, sc);
    context_kernel<<<dim3(2, LK / TL, B), NTHR>>>(value, sc, att, ctx);
}